// round 6
// baseline (speedup 1.0000x reference)
#include <cuda_runtime.h>
#include <cuda_fp16.h>
#include <cuda_bf16.h>

#define NN 50000
#define NE 800000
#define D  64

// ---- scratch (no allocations allowed; __device__ globals) ----
static __device__ int    g_is64;            // 1 if edge_index is int64, 0 if int32
static __device__ int    g_cnt[NN];
static __device__ int    g_cursor[NN];
static __device__ float  g_dis[NN];
static __device__ int    g_rowstart[NN + 1];
static __device__ int    g_csr[NE];                      // src only (norm folded into hs)
static __device__ __align__(128) __half g_h[NN * D];     // hs = (XW)*dis, fp16, 128B rows
static __device__ float  g_buf[NN * D];                  // layer output / next layer input

// ============================================================
// init + dtype sniff (int64 => all high 32-bit words zero)
// ============================================================

__global__ void k_init(const int* __restrict__ ei32) {
    int v = blockIdx.x * blockDim.x + threadIdx.x;
    if (v < NN) { g_cnt[v] = 0; g_cursor[v] = 0; }
    if (blockIdx.x == 0 && threadIdx.x == 0) {
        int all_zero = 1;
        #pragma unroll
        for (int i = 0; i < 64; i++) {
            if (ei32[2 * i + 1] != 0) { all_zero = 0; break; }
        }
        g_is64 = all_zero;
    }
}

__device__ __forceinline__ int load_idx(const void* ei, int pos, int is64) {
    if (is64) return (int)((const long long*)ei)[pos];
    return ((const int*)ei)[pos];
}

// ============================================================
// degree count, scan(+dis), CSR scatter
// ============================================================

__global__ void k_count(const void* __restrict__ ei) {
    int e = blockIdx.x * blockDim.x + threadIdx.x;
    int is64 = g_is64;
    if (e < NE) {
        int dst = load_idx(ei, NE + e, is64);
        atomicAdd(&g_cnt[dst], 1);
    }
}

// Single-block exclusive scan of g_cnt -> g_rowstart, plus deg_inv_sqrt
__global__ void k_scan(void) {
    __shared__ int part[1024];
    const int t = threadIdx.x;
    const int CH = (NN + 1023) / 1024;   // 49
    int lo = t * CH;
    int hi = lo + CH; if (hi > NN) hi = NN; if (lo > NN) lo = NN;
    int s = 0;
    for (int i = lo; i < hi; i++) {
        int c = g_cnt[i];
        g_dis[i] = rsqrtf((float)(c + 1));   // +1 self-loop
        s += c;
    }
    part[t] = s;
    __syncthreads();
    for (int off = 1; off < 1024; off <<= 1) {
        int v = (t >= off) ? part[t - off] : 0;
        __syncthreads();
        part[t] += v;
        __syncthreads();
    }
    int run = (t == 0) ? 0 : part[t - 1];
    for (int i = lo; i < hi; i++) {
        int c = g_cnt[i];
        g_rowstart[i] = run;
        run += c;
    }
    if (t == 1023) g_rowstart[NN] = run;   // == NE
}

__global__ void k_scatter(const void* __restrict__ ei) {
    int e = blockIdx.x * blockDim.x + threadIdx.x;
    int is64 = g_is64;
    if (e < NE) {
        int s = load_idx(ei, e, is64);
        int d = load_idx(ei, NE + e, is64);
        int pos = g_rowstart[d] + atomicAdd(&g_cursor[d], 1);
        g_csr[pos] = s;
    }
}

// ============================================================
// GEMM: g_h = ((relu?)in @ W) * dis[row]   -> fp16 (half2 rows)
// block = 128 threads, tile = 32 rows
// ============================================================

#define XS_STRIDE 34   // padded transposed X tile stride (conflict-free float2 reads)

__global__ void __launch_bounds__(128) k_gemm(const float* __restrict__ Xext,
                                              int use_ext,
                                              const float* __restrict__ W,
                                              int relu) {
    __shared__ float Ws[64 * 64];            // W row-major
    __shared__ float XsT[64 * XS_STRIDE];    // X tile transposed: XsT[k*34 + row]

    const float* __restrict__ X = use_ext ? Xext : g_buf;
    const int t = threadIdx.x;
    const int rbase = blockIdx.x * 32;

    // load W (4096 floats = 1024 float4, 8 per thread)
    {
        const float4* W4 = (const float4*)W;
        float4* Ws4 = (float4*)Ws;
        #pragma unroll
        for (int i = 0; i < 8; i++) Ws4[t + 128 * i] = W4[t + 128 * i];
    }

    // load X tile transposed: thread t -> row t/4, cols [(t%4)*16, +16)
    {
        int row = t >> 2;
        int cb  = (t & 3) * 16;
        int gr  = rbase + row;
        float4 v0, v1, v2, v3;
        if (gr < NN) {
            const float4* Xr = (const float4*)(X + (size_t)gr * D + cb);
            v0 = Xr[0]; v1 = Xr[1]; v2 = Xr[2]; v3 = Xr[3];
            if (relu) {
                v0.x = fmaxf(v0.x, 0.f); v0.y = fmaxf(v0.y, 0.f); v0.z = fmaxf(v0.z, 0.f); v0.w = fmaxf(v0.w, 0.f);
                v1.x = fmaxf(v1.x, 0.f); v1.y = fmaxf(v1.y, 0.f); v1.z = fmaxf(v1.z, 0.f); v1.w = fmaxf(v1.w, 0.f);
                v2.x = fmaxf(v2.x, 0.f); v2.y = fmaxf(v2.y, 0.f); v2.z = fmaxf(v2.z, 0.f); v2.w = fmaxf(v2.w, 0.f);
                v3.x = fmaxf(v3.x, 0.f); v3.y = fmaxf(v3.y, 0.f); v3.z = fmaxf(v3.z, 0.f); v3.w = fmaxf(v3.w, 0.f);
            }
        } else {
            v0 = v1 = v2 = v3 = make_float4(0.f, 0.f, 0.f, 0.f);
        }
        float* col = XsT + row;
        col[(cb +  0) * XS_STRIDE] = v0.x; col[(cb +  1) * XS_STRIDE] = v0.y;
        col[(cb +  2) * XS_STRIDE] = v0.z; col[(cb +  3) * XS_STRIDE] = v0.w;
        col[(cb +  4) * XS_STRIDE] = v1.x; col[(cb +  5) * XS_STRIDE] = v1.y;
        col[(cb +  6) * XS_STRIDE] = v1.z; col[(cb +  7) * XS_STRIDE] = v1.w;
        col[(cb +  8) * XS_STRIDE] = v2.x; col[(cb +  9) * XS_STRIDE] = v2.y;
        col[(cb + 10) * XS_STRIDE] = v2.z; col[(cb + 11) * XS_STRIDE] = v2.w;
        col[(cb + 12) * XS_STRIDE] = v3.x; col[(cb + 13) * XS_STRIDE] = v3.y;
        col[(cb + 14) * XS_STRIDE] = v3.z; col[(cb + 15) * XS_STRIDE] = v3.w;
    }
    __syncthreads();

    const int cg = t & 7;    // col group: cols [8*cg, 8*cg+8)
    const int rp = t >> 3;   // row pair: rows 2*rp, 2*rp+1

    float acc[16];
    #pragma unroll
    for (int i = 0; i < 16; i++) acc[i] = 0.f;

    #pragma unroll 8
    for (int k = 0; k < 64; k++) {
        float2 x01 = *(const float2*)&XsT[k * XS_STRIDE + 2 * rp];
        float4 wa  = *(const float4*)&Ws[k * 64 + 8 * cg];
        float4 wb  = *(const float4*)&Ws[k * 64 + 8 * cg + 4];
        acc[0]  = fmaf(x01.x, wa.x, acc[0]);  acc[1]  = fmaf(x01.x, wa.y, acc[1]);
        acc[2]  = fmaf(x01.x, wa.z, acc[2]);  acc[3]  = fmaf(x01.x, wa.w, acc[3]);
        acc[4]  = fmaf(x01.x, wb.x, acc[4]);  acc[5]  = fmaf(x01.x, wb.y, acc[5]);
        acc[6]  = fmaf(x01.x, wb.z, acc[6]);  acc[7]  = fmaf(x01.x, wb.w, acc[7]);
        acc[8]  = fmaf(x01.y, wa.x, acc[8]);  acc[9]  = fmaf(x01.y, wa.y, acc[9]);
        acc[10] = fmaf(x01.y, wa.z, acc[10]); acc[11] = fmaf(x01.y, wa.w, acc[11]);
        acc[12] = fmaf(x01.y, wb.x, acc[12]); acc[13] = fmaf(x01.y, wb.y, acc[13]);
        acc[14] = fmaf(x01.y, wb.z, acc[14]); acc[15] = fmaf(x01.y, wb.w, acc[15]);
    }

    // epilogue: scale by dis[row], convert to half2, store 16B per row
    int r0 = rbase + 2 * rp;
    if (r0 < NN) {
        float d0 = g_dis[r0];
        alignas(16) __half2 ph[4];
        ph[0] = __floats2half2_rn(acc[0] * d0, acc[1] * d0);
        ph[1] = __floats2half2_rn(acc[2] * d0, acc[3] * d0);
        ph[2] = __floats2half2_rn(acc[4] * d0, acc[5] * d0);
        ph[3] = __floats2half2_rn(acc[6] * d0, acc[7] * d0);
        *(uint4*)&g_h[(size_t)r0 * D + 8 * cg] = *(const uint4*)ph;
    }
    if (r0 + 1 < NN) {
        float d1 = g_dis[r0 + 1];
        alignas(16) __half2 ph[4];
        ph[0] = __floats2half2_rn(acc[8]  * d1, acc[9]  * d1);
        ph[1] = __floats2half2_rn(acc[10] * d1, acc[11] * d1);
        ph[2] = __floats2half2_rn(acc[12] * d1, acc[13] * d1);
        ph[3] = __floats2half2_rn(acc[14] * d1, acc[15] * d1);
        *(uint4*)&g_h[(size_t)(r0 + 1) * D + 8 * cg] = *(const uint4*)ph;
    }
}

// ============================================================
// Aggregation: out[v] = dis[v]*(hs[v] + sum_e hs[src_e]) + b
// one warp per node, lane owns half2 column `lane` (features 2l,2l+1)
// ============================================================

__global__ void __launch_bounds__(256) k_agg(const float* __restrict__ b,
                                             float* __restrict__ dout,
                                             int use_dout) {
    int w = (blockIdx.x * blockDim.x + threadIdx.x) >> 5;
    if (w >= NN) return;
    int lane = threadIdx.x & 31;

    float* __restrict__ out = use_dout ? dout : g_buf;
    const __half2* __restrict__ H = (const __half2*)g_h;   // row stride 32 half2
    const int* __restrict__ C = g_csr;

    float2 acc = __half22float2(H[(size_t)w * 32 + lane]);  // self-loop term

    int e  = g_rowstart[w];
    int e1 = g_rowstart[w + 1];

    for (; e + 4 <= e1; e += 4) {
        int s0 = C[e + 0];
        int s1 = C[e + 1];
        int s2 = C[e + 2];
        int s3 = C[e + 3];
        float2 f0 = __half22float2(H[(size_t)s0 * 32 + lane]);
        float2 f1 = __half22float2(H[(size_t)s1 * 32 + lane]);
        float2 f2 = __half22float2(H[(size_t)s2 * 32 + lane]);
        float2 f3 = __half22float2(H[(size_t)s3 * 32 + lane]);
        acc.x += f0.x; acc.y += f0.y;
        acc.x += f1.x; acc.y += f1.y;
        acc.x += f2.x; acc.y += f2.y;
        acc.x += f3.x; acc.y += f3.y;
    }
    for (; e < e1; e++) {
        int s = C[e];
        float2 f = __half22float2(H[(size_t)s * 32 + lane]);
        acc.x += f.x; acc.y += f.y;
    }

    float dv  = g_dis[w];
    float2 bb = *(const float2*)&b[2 * lane];
    float2 r  = make_float2(fmaf(acc.x, dv, bb.x), fmaf(acc.y, dv, bb.y));
    *(float2*)&out[(size_t)w * D + 2 * lane] = r;
}

// ============================================================
// Launch
// ============================================================

extern "C" void kernel_launch(void* const* d_in, const int* in_sizes, int n_in,
                              void* d_out, int out_size) {
    const float* x  = (const float*)d_in[0];
    const void*  ei = d_in[1];                 // int32 or int64 [2, 800000], sniffed on device
    const float* W0 = (const float*)d_in[2];
    const float* b0 = (const float*)d_in[3];
    const float* W1 = (const float*)d_in[4];
    const float* b1 = (const float*)d_in[5];
    const float* W2 = (const float*)d_in[6];
    const float* b2 = (const float*)d_in[7];
    float* out = (float*)d_out;

    // --- preprocessing: init+sniff, degree count, scan+dis, CSR scatter ---
    k_init   <<<(NN + 255) / 256, 256>>>((const int*)ei);
    k_count  <<<(NE + 255) / 256, 256>>>(ei);
    k_scan   <<<1, 1024>>>();
    k_scatter<<<(NE + 255) / 256, 256>>>(ei);

    const int gemm_grid = (NN + 31) / 32;            // 1563
    const int agg_grid  = (NN * 32 + 255) / 256;     // 6250

    // --- layer 0 ---
    k_gemm<<<gemm_grid, 128>>>(x, 1, W0, 0);
    k_agg <<<agg_grid, 256>>>(b0, out, 0);
    // --- layer 1 (relu fused into GEMM input read) ---
    k_gemm<<<gemm_grid, 128>>>(x, 0, W1, 1);
    k_agg <<<agg_grid, 256>>>(b1, out, 0);
    // --- layer 2 ---
    k_gemm<<<gemm_grid, 128>>>(x, 0, W2, 1);
    k_agg <<<agg_grid, 256>>>(b2, out, 1);   // final result straight to d_out
}

// round 7
// speedup vs baseline: 1.0026x; 1.0026x over previous
#include <cuda_runtime.h>
#include <cuda_fp16.h>
#include <cuda_bf16.h>

#define NN 50000
#define NE 800000
#define D  64

// ---- scratch (no allocations allowed; __device__ globals) ----
static __device__ int    g_is64;            // 1 if edge_index is int64, 0 if int32
static __device__ __align__(16) int g_cnt[NN];
static __device__ int    g_cursor[NN];
static __device__ float  g_dis[NN];
static __device__ int    g_rowstart[NN + 1];
static __device__ int    g_csr[NE];                      // src only (norm folded into hs)
static __device__ __align__(128) __half g_h[NN * D];     // hs = (XW)*dis, fp16, 128B rows
static __device__ float  g_buf[NN * D];                  // layer output / next layer input

// ============================================================
// init + dtype sniff (int64 => all high 32-bit words zero)
// ============================================================

__global__ void k_init(const int* __restrict__ ei32) {
    int v = blockIdx.x * blockDim.x + threadIdx.x;
    if (v < NN) { g_cnt[v] = 0; g_cursor[v] = 0; }
    if (blockIdx.x == 0 && threadIdx.x == 0) {
        int all_zero = 1;
        #pragma unroll
        for (int i = 0; i < 64; i++) {
            if (ei32[2 * i + 1] != 0) { all_zero = 0; break; }
        }
        g_is64 = all_zero;
    }
}

__device__ __forceinline__ int load_idx(const void* ei, int pos, int is64) {
    if (is64) return (int)((const long long*)ei)[pos];
    return ((const int*)ei)[pos];
}

// ============================================================
// degree count (4 edges/thread), scan(+dis), CSR scatter (4 edges/thread)
// ============================================================

__global__ void k_count(const void* __restrict__ ei) {
    int e0 = (blockIdx.x * blockDim.x + threadIdx.x) * 4;
    int is64 = g_is64;
    int d[4];
    #pragma unroll
    for (int j = 0; j < 4; j++)
        d[j] = (e0 + j < NE) ? load_idx(ei, NE + e0 + j, is64) : -1;
    #pragma unroll
    for (int j = 0; j < 4; j++)
        if (d[j] >= 0) atomicAdd(&g_cnt[d[j]], 1);
}

// Single-block exclusive scan of g_cnt -> g_rowstart, plus deg_inv_sqrt
__global__ void k_scan(void) {
    __shared__ int part[1024];
    const int t = threadIdx.x;
    const int CH = (NN + 1023) / 1024;   // 49
    int lo = t * CH;
    int hi = lo + CH; if (hi > NN) hi = NN; if (lo > NN) lo = NN;
    int s = 0;
    #pragma unroll 7
    for (int i = lo; i < hi; i++) {
        int c = g_cnt[i];
        g_dis[i] = rsqrtf((float)(c + 1));   // +1 self-loop
        s += c;
    }
    part[t] = s;
    __syncthreads();
    for (int off = 1; off < 1024; off <<= 1) {
        int v = (t >= off) ? part[t - off] : 0;
        __syncthreads();
        part[t] += v;
        __syncthreads();
    }
    int run = (t == 0) ? 0 : part[t - 1];
    #pragma unroll 7
    for (int i = lo; i < hi; i++) {
        int c = g_cnt[i];
        g_rowstart[i] = run;
        run += c;
    }
    if (t == 1023) g_rowstart[NN] = run;   // == NE
}

__global__ void k_scatter(const void* __restrict__ ei) {
    int e0 = (blockIdx.x * blockDim.x + threadIdx.x) * 4;
    int is64 = g_is64;
    int s[4], d[4];
    #pragma unroll
    for (int j = 0; j < 4; j++) {
        if (e0 + j < NE) {
            s[j] = load_idx(ei, e0 + j, is64);
            d[j] = load_idx(ei, NE + e0 + j, is64);
        } else { s[j] = -1; d[j] = 0; }
    }
    int base[4];
    #pragma unroll
    for (int j = 0; j < 4; j++)
        base[j] = (s[j] >= 0) ? g_rowstart[d[j]] : 0;
    #pragma unroll
    for (int j = 0; j < 4; j++) {
        if (s[j] >= 0) {
            int pos = base[j] + atomicAdd(&g_cursor[d[j]], 1);
            g_csr[pos] = s[j];
        }
    }
}

// ============================================================
// GEMM: g_h = ((relu?)in @ W) * dis[row]   -> fp16 (half2 rows)
// block = 128 threads, tile = 32 rows
// ============================================================

#define XS_STRIDE 34   // padded transposed X tile stride (conflict-free float2 reads)

__global__ void __launch_bounds__(128) k_gemm(const float* __restrict__ Xext,
                                              int use_ext,
                                              const float* __restrict__ W,
                                              int relu) {
    __shared__ float Ws[64 * 64];            // W row-major
    __shared__ float XsT[64 * XS_STRIDE];    // X tile transposed: XsT[k*34 + row]

    const float* __restrict__ X = use_ext ? Xext : g_buf;
    const int t = threadIdx.x;
    const int rbase = blockIdx.x * 32;

    // load W (4096 floats = 1024 float4, 8 per thread)
    {
        const float4* W4 = (const float4*)W;
        float4* Ws4 = (float4*)Ws;
        #pragma unroll
        for (int i = 0; i < 8; i++) Ws4[t + 128 * i] = W4[t + 128 * i];
    }

    // load X tile transposed: thread t -> row t/4, cols [(t%4)*16, +16)
    {
        int row = t >> 2;
        int cb  = (t & 3) * 16;
        int gr  = rbase + row;
        float4 v0, v1, v2, v3;
        if (gr < NN) {
            const float4* Xr = (const float4*)(X + (size_t)gr * D + cb);
            v0 = Xr[0]; v1 = Xr[1]; v2 = Xr[2]; v3 = Xr[3];
            if (relu) {
                v0.x = fmaxf(v0.x, 0.f); v0.y = fmaxf(v0.y, 0.f); v0.z = fmaxf(v0.z, 0.f); v0.w = fmaxf(v0.w, 0.f);
                v1.x = fmaxf(v1.x, 0.f); v1.y = fmaxf(v1.y, 0.f); v1.z = fmaxf(v1.z, 0.f); v1.w = fmaxf(v1.w, 0.f);
                v2.x = fmaxf(v2.x, 0.f); v2.y = fmaxf(v2.y, 0.f); v2.z = fmaxf(v2.z, 0.f); v2.w = fmaxf(v2.w, 0.f);
                v3.x = fmaxf(v3.x, 0.f); v3.y = fmaxf(v3.y, 0.f); v3.z = fmaxf(v3.z, 0.f); v3.w = fmaxf(v3.w, 0.f);
            }
        } else {
            v0 = v1 = v2 = v3 = make_float4(0.f, 0.f, 0.f, 0.f);
        }
        float* col = XsT + row;
        col[(cb +  0) * XS_STRIDE] = v0.x; col[(cb +  1) * XS_STRIDE] = v0.y;
        col[(cb +  2) * XS_STRIDE] = v0.z; col[(cb +  3) * XS_STRIDE] = v0.w;
        col[(cb +  4) * XS_STRIDE] = v1.x; col[(cb +  5) * XS_STRIDE] = v1.y;
        col[(cb +  6) * XS_STRIDE] = v1.z; col[(cb +  7) * XS_STRIDE] = v1.w;
        col[(cb +  8) * XS_STRIDE] = v2.x; col[(cb +  9) * XS_STRIDE] = v2.y;
        col[(cb + 10) * XS_STRIDE] = v2.z; col[(cb + 11) * XS_STRIDE] = v2.w;
        col[(cb + 12) * XS_STRIDE] = v3.x; col[(cb + 13) * XS_STRIDE] = v3.y;
        col[(cb + 14) * XS_STRIDE] = v3.z; col[(cb + 15) * XS_STRIDE] = v3.w;
    }
    __syncthreads();

    const int cg = t & 7;    // col group: cols [8*cg, 8*cg+8)
    const int rp = t >> 3;   // row pair: rows 2*rp, 2*rp+1

    float acc[16];
    #pragma unroll
    for (int i = 0; i < 16; i++) acc[i] = 0.f;

    #pragma unroll 8
    for (int k = 0; k < 64; k++) {
        float2 x01 = *(const float2*)&XsT[k * XS_STRIDE + 2 * rp];
        float4 wa  = *(const float4*)&Ws[k * 64 + 8 * cg];
        float4 wb  = *(const float4*)&Ws[k * 64 + 8 * cg + 4];
        acc[0]  = fmaf(x01.x, wa.x, acc[0]);  acc[1]  = fmaf(x01.x, wa.y, acc[1]);
        acc[2]  = fmaf(x01.x, wa.z, acc[2]);  acc[3]  = fmaf(x01.x, wa.w, acc[3]);
        acc[4]  = fmaf(x01.x, wb.x, acc[4]);  acc[5]  = fmaf(x01.x, wb.y, acc[5]);
        acc[6]  = fmaf(x01.x, wb.z, acc[6]);  acc[7]  = fmaf(x01.x, wb.w, acc[7]);
        acc[8]  = fmaf(x01.y, wa.x, acc[8]);  acc[9]  = fmaf(x01.y, wa.y, acc[9]);
        acc[10] = fmaf(x01.y, wa.z, acc[10]); acc[11] = fmaf(x01.y, wa.w, acc[11]);
        acc[12] = fmaf(x01.y, wb.x, acc[12]); acc[13] = fmaf(x01.y, wb.y, acc[13]);
        acc[14] = fmaf(x01.y, wb.z, acc[14]); acc[15] = fmaf(x01.y, wb.w, acc[15]);
    }

    // epilogue: scale by dis[row], convert to half2, store 16B per row
    int r0 = rbase + 2 * rp;
    if (r0 < NN) {
        float d0 = g_dis[r0];
        alignas(16) __half2 ph[4];
        ph[0] = __floats2half2_rn(acc[0] * d0, acc[1] * d0);
        ph[1] = __floats2half2_rn(acc[2] * d0, acc[3] * d0);
        ph[2] = __floats2half2_rn(acc[4] * d0, acc[5] * d0);
        ph[3] = __floats2half2_rn(acc[6] * d0, acc[7] * d0);
        *(uint4*)&g_h[(size_t)r0 * D + 8 * cg] = *(const uint4*)ph;
    }
    if (r0 + 1 < NN) {
        float d1 = g_dis[r0 + 1];
        alignas(16) __half2 ph[4];
        ph[0] = __floats2half2_rn(acc[8]  * d1, acc[9]  * d1);
        ph[1] = __floats2half2_rn(acc[10] * d1, acc[11] * d1);
        ph[2] = __floats2half2_rn(acc[12] * d1, acc[13] * d1);
        ph[3] = __floats2half2_rn(acc[14] * d1, acc[15] * d1);
        *(uint4*)&g_h[(size_t)(r0 + 1) * D + 8 * cg] = *(const uint4*)ph;
    }
}

// ============================================================
// Aggregation: out[v] = dis[v]*(hs[v] + sum_e hs[src_e]) + b
// one warp per node; lane -> (slot = lane/8 edge slot, ch = lane%8 16B chunk)
// one LDG.128 gathers 4 edges' rows per warp instruction
// ============================================================

__device__ __forceinline__ void acc_row16(float acc[8], uint4 q) {
    __half2 h0 = *(__half2*)&q.x;
    __half2 h1 = *(__half2*)&q.y;
    __half2 h2 = *(__half2*)&q.z;
    __half2 h3 = *(__half2*)&q.w;
    float2 f0 = __half22float2(h0);
    float2 f1 = __half22float2(h1);
    float2 f2 = __half22float2(h2);
    float2 f3 = __half22float2(h3);
    acc[0] += f0.x; acc[1] += f0.y;
    acc[2] += f1.x; acc[3] += f1.y;
    acc[4] += f2.x; acc[5] += f2.y;
    acc[6] += f3.x; acc[7] += f3.y;
}

__global__ void __launch_bounds__(256) k_agg(const float* __restrict__ b,
                                             float* __restrict__ dout,
                                             int use_dout) {
    int w = (blockIdx.x * blockDim.x + threadIdx.x) >> 5;
    if (w >= NN) return;
    int lane = threadIdx.x & 31;
    int slot = lane >> 3;   // 0..3: which edge in the 4-pack
    int ch   = lane & 7;    // 16B chunk within the 128B row

    float* __restrict__ out = use_dout ? dout : g_buf;
    const uint4* __restrict__ H4 = (const uint4*)g_h;   // row = 8 uint4
    const int* __restrict__ C = g_csr;

    float acc[8];
    #pragma unroll
    for (int i = 0; i < 8; i++) acc[i] = 0.f;

    // self-loop term (only slot 0 contributes; others would quadruple-count)
    if (slot == 0) acc_row16(acc, H4[(size_t)w * 8 + ch]);

    int e  = g_rowstart[w];
    int e1 = g_rowstart[w + 1];

    #pragma unroll 2
    for (; e + 4 <= e1; e += 4) {
        int idx = C[e + slot];
        acc_row16(acc, H4[(size_t)idx * 8 + ch]);
    }
    if (e < e1 && slot < (e1 - e)) {
        int idx = C[e + slot];
        acc_row16(acc, H4[(size_t)idx * 8 + ch]);
    }

    // reduce across the 4 edge slots (lanes differing in bits 3,4 of lane id)
    #pragma unroll
    for (int i = 0; i < 8; i++) {
        acc[i] += __shfl_xor_sync(0xFFFFFFFFu, acc[i], 8);
        acc[i] += __shfl_xor_sync(0xFFFFFFFFu, acc[i], 16);
    }

    if (slot == 0) {
        float dv = g_dis[w];
        float4 b0 = *(const float4*)&b[ch * 8];
        float4 b1 = *(const float4*)&b[ch * 8 + 4];
        float4 o0 = make_float4(fmaf(acc[0], dv, b0.x), fmaf(acc[1], dv, b0.y),
                                fmaf(acc[2], dv, b0.z), fmaf(acc[3], dv, b0.w));
        float4 o1 = make_float4(fmaf(acc[4], dv, b1.x), fmaf(acc[5], dv, b1.y),
                                fmaf(acc[6], dv, b1.z), fmaf(acc[7], dv, b1.w));
        float4* op = (float4*)&out[(size_t)w * D + ch * 8];
        op[0] = o0;
        op[1] = o1;
    }
}

// ============================================================
// Launch
// ============================================================

extern "C" void kernel_launch(void* const* d_in, const int* in_sizes, int n_in,
                              void* d_out, int out_size) {
    const float* x  = (const float*)d_in[0];
    const void*  ei = d_in[1];                 // int32 or int64 [2, 800000], sniffed on device
    const float* W0 = (const float*)d_in[2];
    const float* b0 = (const float*)d_in[3];
    const float* W1 = (const float*)d_in[4];
    const float* b1 = (const float*)d_in[5];
    const float* W2 = (const float*)d_in[6];
    const float* b2 = (const float*)d_in[7];
    float* out = (float*)d_out;

    // --- preprocessing: init+sniff, degree count, scan+dis, CSR scatter ---
    const int eth = (NE / 4 + 255) / 256;            // 4 edges per thread
    k_init   <<<(NN + 255) / 256, 256>>>((const int*)ei);
    k_count  <<<eth, 256>>>(ei);
    k_scan   <<<1, 1024>>>();
    k_scatter<<<eth, 256>>>(ei);

    const int gemm_grid = (NN + 31) / 32;            // 1563
    const int agg_grid  = (NN * 32 + 255) / 256;     // 6250

    // --- layer 0 ---
    k_gemm<<<gemm_grid, 128>>>(x, 1, W0, 0);
    k_agg <<<agg_grid, 256>>>(b0, out, 0);
    // --- layer 1 (relu fused into GEMM input read) ---
    k_gemm<<<gemm_grid, 128>>>(x, 0, W1, 1);
    k_agg <<<agg_grid, 256>>>(b1, out, 0);
    // --- layer 2 ---
    k_gemm<<<gemm_grid, 128>>>(x, 0, W2, 1);
    k_agg <<<agg_grid, 256>>>(b2, out, 1);   // final result straight to d_out
}

// round 10
// speedup vs baseline: 1.1889x; 1.1858x over previous
#include <cuda_runtime.h>
#include <cuda_fp16.h>

#define NN 50000
#define NE 800000
#define D  64
#define NB 592                    // 4 blocks/SM x 148 SMs (GB300 has >=148)
#define NT 256
#define NWARP (NB * (NT / 32))    // 4736 warps
#define NBAR 11
#define NTILE ((NN + 63) / 64)    // 782 gemm tiles (64 rows per tile, 256 threads)
#define XS_STRIDE 66              // 64 rows + pad, conflict-free float2 reads

// ---- scratch (no allocations allowed; __device__ globals, zero-initialized) ----
static __device__ int      g_is64;
static __device__ int      g_cnt[NN];
static __device__ int      g_cursor[NN];
static __device__ float    g_dis[NN];
static __device__ int      g_rowstart[NN + 1];
static __device__ int      g_csr[NE];                      // src only
static __device__ __align__(128) __half g_h[NN * D];       // hs = (XW)*dis, fp16
static __device__ float    g_buf[NN * D];
static __device__ int      g_bsum[NB];
static __device__ int      g_boff[NB];
static __device__ unsigned g_bar[NBAR];   // monotonic arrival counters, never reset

// ============================================================
// device-wide barrier: monotonic per-slot counters, replay-safe
// ============================================================
__device__ __forceinline__ void gbar(int& bi, unsigned target) {
    __threadfence();              // release: push this thread's writes to L2
    __syncthreads();
    if (threadIdx.x == 0) {
        unsigned p = atomicAdd(&g_bar[bi], 1u) + 1u;
        if (p < target) {
            while (*(volatile unsigned*)&g_bar[bi] < target) __nanosleep(64);
        }
    }
    __syncthreads();
    __threadfence();              // acquire: gpu-scope fence -> no stale L1 reads
    bi++;
}

// block-wide exclusive scan of one int per thread; returns excl, sets *btot
__device__ __forceinline__ int block_escan(int c, int* btot, int* s_w) {
    int lane = threadIdx.x & 31, wd = threadIdx.x >> 5;
    int v = c;
    #pragma unroll
    for (int o = 1; o < 32; o <<= 1) {
        int n = __shfl_up_sync(0xFFFFFFFFu, v, o);
        if (lane >= o) v += n;
    }
    if (lane == 31) s_w[wd] = v;
    __syncthreads();
    if (wd == 0 && lane < 8) {
        int w = s_w[lane];
        #pragma unroll
        for (int o = 1; o < 8; o <<= 1) {
            int n = __shfl_up_sync(0xFFu, w, o);
            if (lane >= o) w += n;
        }
        s_w[lane] = w;
    }
    __syncthreads();
    int excl = v - c + (wd ? s_w[wd - 1] : 0);
    *btot = s_w[7];
    return excl;
}

__device__ __forceinline__ int load_idx(const void* ei, int pos, int is64) {
    if (is64) return (int)((const long long*)ei)[pos];
    return ((const int*)ei)[pos];
}

// ============================================================
// phase: GEMM  g_h = ((relu?)X @ W) * dis[row], fp16 out
// 256 threads, 64-row tiles
// ============================================================
__device__ __forceinline__ void phase_gemm(const float* __restrict__ X,
                                           const float* __restrict__ W,
                                           int relu, float* s_Ws, float* s_XsT) {
    const int t = threadIdx.x;
    {   // load W once per layer: 4096 floats = 1024 float4, 4 per thread (256 threads)
        const float4* W4 = (const float4*)W;
        float4* Ws4 = (float4*)s_Ws;
        #pragma unroll
        for (int i = 0; i < 4; i++) Ws4[t + 256 * i] = W4[t + 256 * i];
    }
    for (int tb = blockIdx.x; tb < NTILE; tb += NB) {
        __syncthreads();   // orders prior-iter reads (and the W load) before XsT writes
        const int rbase = tb * 64;
        {   // load X tile transposed: thread t -> row t/4 (0..63), cols [(t%4)*16, +16)
            int row = t >> 2;
            int cb  = (t & 3) * 16;
            int gr  = rbase + row;
            float4 v0, v1, v2, v3;
            if (gr < NN) {
                const float4* Xr = (const float4*)(X + (size_t)gr * D + cb);
                v0 = Xr[0]; v1 = Xr[1]; v2 = Xr[2]; v3 = Xr[3];
                if (relu) {
                    v0.x = fmaxf(v0.x, 0.f); v0.y = fmaxf(v0.y, 0.f); v0.z = fmaxf(v0.z, 0.f); v0.w = fmaxf(v0.w, 0.f);
                    v1.x = fmaxf(v1.x, 0.f); v1.y = fmaxf(v1.y, 0.f); v1.z = fmaxf(v1.z, 0.f); v1.w = fmaxf(v1.w, 0.f);
                    v2.x = fmaxf(v2.x, 0.f); v2.y = fmaxf(v2.y, 0.f); v2.z = fmaxf(v2.z, 0.f); v2.w = fmaxf(v2.w, 0.f);
                    v3.x = fmaxf(v3.x, 0.f); v3.y = fmaxf(v3.y, 0.f); v3.z = fmaxf(v3.z, 0.f); v3.w = fmaxf(v3.w, 0.f);
                }
            } else {
                v0 = v1 = v2 = v3 = make_float4(0.f, 0.f, 0.f, 0.f);
            }
            float* col = s_XsT + row;
            col[(cb +  0) * XS_STRIDE] = v0.x; col[(cb +  1) * XS_STRIDE] = v0.y;
            col[(cb +  2) * XS_STRIDE] = v0.z; col[(cb +  3) * XS_STRIDE] = v0.w;
            col[(cb +  4) * XS_STRIDE] = v1.x; col[(cb +  5) * XS_STRIDE] = v1.y;
            col[(cb +  6) * XS_STRIDE] = v1.z; col[(cb +  7) * XS_STRIDE] = v1.w;
            col[(cb +  8) * XS_STRIDE] = v2.x; col[(cb +  9) * XS_STRIDE] = v2.y;
            col[(cb + 10) * XS_STRIDE] = v2.z; col[(cb + 11) * XS_STRIDE] = v2.w;
            col[(cb + 12) * XS_STRIDE] = v3.x; col[(cb + 13) * XS_STRIDE] = v3.y;
            col[(cb + 14) * XS_STRIDE] = v3.z; col[(cb + 15) * XS_STRIDE] = v3.w;
        }
        __syncthreads();

        const int cg = t & 7;    // col group: cols [8*cg, 8*cg+8)
        const int rp = t >> 3;   // row pair 0..31 -> rows 2*rp, 2*rp+1 (0..63)

        float acc[16];
        #pragma unroll
        for (int i = 0; i < 16; i++) acc[i] = 0.f;

        #pragma unroll 8
        for (int k = 0; k < 64; k++) {
            float2 x01 = *(const float2*)&s_XsT[k * XS_STRIDE + 2 * rp];
            float4 wa  = *(const float4*)&s_Ws[k * 64 + 8 * cg];
            float4 wb  = *(const float4*)&s_Ws[k * 64 + 8 * cg + 4];
            acc[0]  = fmaf(x01.x, wa.x, acc[0]);  acc[1]  = fmaf(x01.x, wa.y, acc[1]);
            acc[2]  = fmaf(x01.x, wa.z, acc[2]);  acc[3]  = fmaf(x01.x, wa.w, acc[3]);
            acc[4]  = fmaf(x01.x, wb.x, acc[4]);  acc[5]  = fmaf(x01.x, wb.y, acc[5]);
            acc[6]  = fmaf(x01.x, wb.z, acc[6]);  acc[7]  = fmaf(x01.x, wb.w, acc[7]);
            acc[8]  = fmaf(x01.y, wa.x, acc[8]);  acc[9]  = fmaf(x01.y, wa.y, acc[9]);
            acc[10] = fmaf(x01.y, wa.z, acc[10]); acc[11] = fmaf(x01.y, wa.w, acc[11]);
            acc[12] = fmaf(x01.y, wb.x, acc[12]); acc[13] = fmaf(x01.y, wb.y, acc[13]);
            acc[14] = fmaf(x01.y, wb.z, acc[14]); acc[15] = fmaf(x01.y, wb.w, acc[15]);
        }

        int r0 = rbase + 2 * rp;
        if (r0 < NN) {
            float d0 = g_dis[r0];
            alignas(16) __half2 ph[4];
            ph[0] = __floats2half2_rn(acc[0] * d0, acc[1] * d0);
            ph[1] = __floats2half2_rn(acc[2] * d0, acc[3] * d0);
            ph[2] = __floats2half2_rn(acc[4] * d0, acc[5] * d0);
            ph[3] = __floats2half2_rn(acc[6] * d0, acc[7] * d0);
            *(uint4*)&g_h[(size_t)r0 * D + 8 * cg] = *(const uint4*)ph;
        }
        if (r0 + 1 < NN) {
            float d1 = g_dis[r0 + 1];
            alignas(16) __half2 ph[4];
            ph[0] = __floats2half2_rn(acc[8]  * d1, acc[9]  * d1);
            ph[1] = __floats2half2_rn(acc[10] * d1, acc[11] * d1);
            ph[2] = __floats2half2_rn(acc[12] * d1, acc[13] * d1);
            ph[3] = __floats2half2_rn(acc[14] * d1, acc[15] * d1);
            *(uint4*)&g_h[(size_t)(r0 + 1) * D + 8 * cg] = *(const uint4*)ph;
        }
    }
}

// ============================================================
// phase: aggregation  out[v] = dis[v]*(hs[v] + sum_e hs[src_e]) + b
// warp per node, grid-stride; lane owns half2 column `lane`
// ============================================================
__device__ __forceinline__ void phase_agg(const float* __restrict__ b,
                                          float* __restrict__ out) {
    int gw   = (blockIdx.x * NT + threadIdx.x) >> 5;
    int lane = threadIdx.x & 31;
    const __half2* __restrict__ H = (const __half2*)g_h;   // row stride = 32 half2
    const int* __restrict__ C = g_csr;
    float2 bb = *(const float2*)&b[2 * lane];

    for (int w = gw; w < NN; w += NWARP) {
        float2 acc = __half22float2(H[(size_t)w * 32 + lane]);   // self-loop
        int e  = g_rowstart[w];
        int e1 = g_rowstart[w + 1];

        for (; e + 4 <= e1; e += 4) {
            int s0 = C[e + 0], s1 = C[e + 1], s2 = C[e + 2], s3 = C[e + 3];
            float2 f0 = __half22float2(H[(size_t)s0 * 32 + lane]);
            float2 f1 = __half22float2(H[(size_t)s1 * 32 + lane]);
            float2 f2 = __half22float2(H[(size_t)s2 * 32 + lane]);
            float2 f3 = __half22float2(H[(size_t)s3 * 32 + lane]);
            acc.x += f0.x; acc.y += f0.y;
            acc.x += f1.x; acc.y += f1.y;
            acc.x += f2.x; acc.y += f2.y;
            acc.x += f3.x; acc.y += f3.y;
        }
        for (; e < e1; e++) {
            float2 f = __half22float2(H[(size_t)C[e] * 32 + lane]);
            acc.x += f.x; acc.y += f.y;
        }

        float dv = g_dis[w];
        *(float2*)&out[(size_t)w * D + 2 * lane] =
            make_float2(fmaf(acc.x, dv, bb.x), fmaf(acc.y, dv, bb.y));
    }
}

// ============================================================
// the megakernel: all phases, device-wide barriers between them
// ============================================================
__global__ void __launch_bounds__(NT, 4)
k_mega(const float* __restrict__ x, const void* __restrict__ ei,
       const float* __restrict__ W0, const float* __restrict__ b0,
       const float* __restrict__ W1, const float* __restrict__ b1,
       const float* __restrict__ W2, const float* __restrict__ b2,
       float* __restrict__ out) {
    __shared__ float s_Ws[64 * 64];
    __shared__ float s_XsT[64 * XS_STRIDE];
    __shared__ int   s_w[8];

    const int tid  = threadIdx.x;
    const int gtid = blockIdx.x * NT + tid;
    const int gsz  = NB * NT;

    // replay-safe barrier baseline: slot 10 can't be bumped before every block
    // has passed bar 0, which orders all baseline reads before any bump.
    unsigned target = *(volatile unsigned*)&g_bar[NBAR - 1] + (unsigned)NB;
    int bi = 0;

    // ---- A: init counters + dtype sniff ----
    for (int v = gtid; v < NN; v += gsz) { g_cnt[v] = 0; g_cursor[v] = 0; }
    if (gtid == 0) {
        const int* e32 = (const int*)ei;
        int all_zero = 1;
        #pragma unroll
        for (int i = 0; i < 64; i++)
            if (e32[2 * i + 1] != 0) { all_zero = 0; break; }
        g_is64 = all_zero;
    }
    gbar(bi, target);                                   // bar 0

    // ---- B: degree count (4 edges/thread) ----
    {
        int is64 = g_is64;
        for (int e0 = gtid * 4; e0 < NE; e0 += gsz * 4) {
            int dd[4];
            #pragma unroll
            for (int j = 0; j < 4; j++)
                dd[j] = (e0 + j < NE) ? load_idx(ei, NE + e0 + j, is64) : -1;
            #pragma unroll
            for (int j = 0; j < 4; j++)
                if (dd[j] >= 0) atomicAdd(&g_cnt[dd[j]], 1);
        }
    }
    gbar(bi, target);                                   // bar 1

    // ---- C: hierarchical exclusive scan (node gtid per thread) + dis ----
    int my_c = 0, my_excl = 0;
    {
        int v = gtid;
        if (v < NN) {
            my_c = g_cnt[v];
            g_dis[v] = rsqrtf((float)(my_c + 1));
        }
        int btot;
        my_excl = block_escan(my_c, &btot, s_w);
        if (tid == 0) g_bsum[blockIdx.x] = btot;
    }
    gbar(bi, target);                                   // bar 2

    if (blockIdx.x == 0) {   // scan the 592 block sums (3 per thread)
        int base = tid * 3;
        int s0 = (base + 0 < NB) ? g_bsum[base + 0] : 0;
        int s1 = (base + 1 < NB) ? g_bsum[base + 1] : 0;
        int s2 = (base + 2 < NB) ? g_bsum[base + 2] : 0;
        int btot;
        int te = block_escan(s0 + s1 + s2, &btot, s_w);
        if (base + 0 < NB) g_boff[base + 0] = te;
        if (base + 1 < NB) g_boff[base + 1] = te + s0;
        if (base + 2 < NB) g_boff[base + 2] = te + s0 + s1;
    }
    gbar(bi, target);                                   // bar 3

    {
        int v = gtid;
        if (v < NN) {
            int rs = g_boff[blockIdx.x] + my_excl;
            g_rowstart[v] = rs;
            if (v == NN - 1) g_rowstart[NN] = rs + my_c;   // == NE
        }
    }
    gbar(bi, target);                                   // bar 4

    // ---- D: CSR scatter (4 edges/thread) ----
    {
        int is64 = g_is64;
        for (int e0 = gtid * 4; e0 < NE; e0 += gsz * 4) {
            int ss[4], dd[4];
            #pragma unroll
            for (int j = 0; j < 4; j++) {
                if (e0 + j < NE) {
                    ss[j] = load_idx(ei, e0 + j, is64);
                    dd[j] = load_idx(ei, NE + e0 + j, is64);
                } else { ss[j] = -1; dd[j] = 0; }
            }
            int base[4];
            #pragma unroll
            for (int j = 0; j < 4; j++)
                base[j] = (ss[j] >= 0) ? g_rowstart[dd[j]] : 0;
            #pragma unroll
            for (int j = 0; j < 4; j++)
                if (ss[j] >= 0) {
                    int pos = base[j] + atomicAdd(&g_cursor[dd[j]], 1);
                    g_csr[pos] = ss[j];
                }
        }
    }
    gbar(bi, target);                                   // bar 5

    // ---- 3 GCN layers ----
    phase_gemm(x,     W0, 0, s_Ws, s_XsT);  gbar(bi, target);   // bar 6
    phase_agg (b0, g_buf);                  gbar(bi, target);   // bar 7
    phase_gemm(g_buf, W1, 1, s_Ws, s_XsT);  gbar(bi, target);   // bar 8
    phase_agg (b1, g_buf);                  gbar(bi, target);   // bar 9
    phase_gemm(g_buf, W2, 1, s_Ws, s_XsT);  gbar(bi, target);   // bar 10
    phase_agg (b2, out);                    // final: straight to d_out
}

// ============================================================
// Launch: ONE kernel
// ============================================================
extern "C" void kernel_launch(void* const* d_in, const int* in_sizes, int n_in,
                              void* d_out, int out_size) {
    const float* x  = (const float*)d_in[0];
    const void*  ei = d_in[1];
    const float* W0 = (const float*)d_in[2];
    const float* b0 = (const float*)d_in[3];
    const float* W1 = (const float*)d_in[4];
    const float* b1 = (const float*)d_in[5];
    const float* W2 = (const float*)d_in[6];
    const float* b2 = (const float*)d_in[7];
    float* out = (float*)d_out;

    k_mega<<<NB, NT>>>(x, ei, W0, b0, W1, b1, W2, b2, out);
}